// round 11
// baseline (speedup 1.0000x reference)
#include <cuda_runtime.h>
#include <cuda_bf16.h>

#define FULL 0xFFFFFFFFu

constexpr int BATCH = 4096;
constexpr int DIM   = 32;
constexpr int N_MEM = 32;
constexpr int N_REL = 64;
constexpr int NCOL  = N_REL * DIM;   // 2048
constexpr int NB    = 296;           // persistent blocks: 2/SM x 148, guaranteed resident
constexpr int NWARP = NB * 8;        // 2368 persistent warps

// Static scratch (no runtime allocation allowed).
__device__ __nv_bfloat16  g_U[BATCH * NCOL];        // 16 MB bf16, LINEAR [b][n]
__device__ float          g_item[BATCH * DIM];
__device__ unsigned       g_Afrag[(BATCH / 16) * 2 * 32 * 4];   // A MMA frags
__device__ unsigned       g_Bfrag[(NCOL / 64) * 8 * 32 * 4];    // B MMA frags
__device__ float          g_Wt[DIM * DIM];
__device__ float          g_y[BATCH * DIM];

// Device-wide barrier state (generation-relative: replay-safe).
__device__ unsigned           g_cnt = 0;
__device__ volatile unsigned  g_gen = 0;

__device__ __forceinline__ void grid_barrier() {
    __syncthreads();
    if (threadIdx.x == 0) {
        __threadfence();                       // release prior writes
        const unsigned gen = g_gen;
        if (atomicAdd(&g_cnt, 1) == NB - 1) {
            atomicExch(&g_cnt, 0);
            __threadfence();
            g_gen = gen + 1;                   // release
        } else {
            while (g_gen == gen) __nanosleep(64);
        }
        __threadfence();                       // acquire
    }
    __syncthreads();
}

__device__ __forceinline__ float bf_lo(unsigned u) { return __uint_as_float(u << 16); }
__device__ __forceinline__ float bf_hi(unsigned u) { return __uint_as_float(u & 0xFFFF0000u); }

// Scatter one bf16 of the item vector into A-fragment layout.
__device__ __forceinline__ void afrag_store(int b, int e, float v) {
    const int mg = b >> 4, r = b & 15;
    const int h  = e >> 4, k = e & 15, kp = k >> 1;
    const int sel = ((r >> 3) & 1) + 2 * (kp >> 2);
    const int l   = (r & 7) * 4 + (kp & 3);
    const int idx = ((mg * 2 + h) * 32 + l) * 4 + sel;
    ((__nv_bfloat16*)g_Afrag)[idx * 2 + (k & 1)] = __float2bfloat16(v);
}

__device__ __forceinline__ void mma16816(float c[4], const unsigned* a,
                                         unsigned b0, unsigned b1) {
    asm volatile(
        "mma.sync.aligned.m16n8k16.row.col.f32.bf16.bf16.f32 "
        "{%0,%1,%2,%3}, {%4,%5,%6,%7}, {%8,%9}, {%0,%1,%2,%3};\n"
        : "+f"(c[0]), "+f"(c[1]), "+f"(c[2]), "+f"(c[3])
        : "r"(a[0]), "r"(a[1]), "r"(a[2]), "r"(a[3]), "r"(b0), "r"(b1));
}

constexpr int OSTR = 144;   // bytes per sO row (128 payload + 16 pad)

// ---------------------------------------------------------------- phases
__device__ void gemm_phase(char* smem) {
    const int lane = threadIdx.x & 31;
    const int warp = threadIdx.x >> 5;
    char* __restrict__ so = smem + warp * (16 * OSTR);

    const uint4* __restrict__ Af = (const uint4*)g_Afrag;
    const uint4* __restrict__ Bf = (const uint4*)g_Bfrag;
    char* __restrict__ gU = (char*)g_U;

    for (int tile = blockIdx.x; tile < 1024; tile += NB) {
        const int mt = tile >> 5, nt = tile & 31;
        const int mg = mt * 8 + warp;
        const int m0 = mt * 128, n0 = nt * 64;

        const uint4 qa0 = Af[(mg * 2 + 0) * 32 + lane];
        const uint4 qa1 = Af[(mg * 2 + 1) * 32 + lane];
        uint4 qb[8];
        #pragma unroll
        for (int j = 0; j < 8; ++j)
            qb[j] = Bf[(nt * 8 + j) * 32 + lane];

        #pragma unroll
        for (int j = 0; j < 8; ++j) {
            float c[4] = {0.f, 0.f, 0.f, 0.f};
            mma16816(c, (const unsigned*)&qa0, qb[j].x, qb[j].y);
            mma16816(c, (const unsigned*)&qa1, qb[j].z, qb[j].w);
            const __nv_bfloat162 p01 = __float22bfloat162_rn(make_float2(c[0], c[1]));
            const __nv_bfloat162 p23 = __float22bfloat162_rn(make_float2(c[2], c[3]));
            const int row  = lane >> 2;
            const int colb = (8 * j + 2 * (lane & 3)) * 2;
            *(__nv_bfloat162*)(so + row * OSTR + colb)       = p01;
            *(__nv_bfloat162*)(so + (row + 8) * OSTR + colb) = p23;
        }
        __syncwarp();

        #pragma unroll
        for (int i = 0; i < 4; ++i) {
            const int idx = lane + 32 * i;
            const int row = idx >> 3, ch = idx & 7;
            const uint4 v = *(const uint4*)(so + row * OSTR + ch * 16);
            *(uint4*)(gU + ((size_t)(m0 + warp * 16 + row) * NCOL + n0) * 2 + ch * 16) = v;
        }
        __syncwarp();
    }
}

__device__ void attn_phase(char* smem,
                           const int* __restrict__ mem_h,
                           const int* __restrict__ mem_r,
                           const int* __restrict__ mem_t,
                           const int* __restrict__ users,
                           const float* __restrict__ entity,
                           const float* __restrict__ user_table,
                           float* __restrict__ out,
                           int hop, int last)
{
    const int lane = threadIdx.x & 31;
    const int warp = threadIdx.x >> 5;
    const int gwarp = blockIdx.x * 8 + warp;
    float* __restrict__ Pw = (float*)smem + warp * (N_MEM * 9);

    const int mq = lane >> 3;
    const int c  = lane & 7;

    for (int b = gwarp; b < BATCH; b += NWARP) {
        const int base = hop * BATCH * N_MEM + b * N_MEM;
        const int hidx = mem_h[base + lane];
        const int ridx = mem_r[base + lane];
        const int tidx = mem_t[base + lane];

        const float item = g_item[b * DIM + lane];
        const __nv_bfloat16* __restrict__ Ub = g_U + (size_t)b * NCOL;

        #pragma unroll
        for (int stage = 0; stage < 2; ++stage) {
            uint2  uu[4];
            float4 h4[4];
            #pragma unroll
            for (int it = 0; it < 4; ++it) {
                const int m = stage * 16 + it * 4 + mq;
                const int r_i = __shfl_sync(FULL, ridx, m);
                const int h_i = __shfl_sync(FULL, hidx, m);
                uu[it] = *(const uint2*)(Ub + r_i * DIM + 4 * c);
                h4[it] = *(const float4*)(entity + h_i * DIM + 4 * c);
            }
            #pragma unroll
            for (int it = 0; it < 4; ++it) {
                const int m = stage * 16 + it * 4 + mq;
                Pw[m * 9 + c] = bf_lo(uu[it].x) * h4[it].x + bf_hi(uu[it].x) * h4[it].y +
                                bf_lo(uu[it].y) * h4[it].z + bf_hi(uu[it].y) * h4[it].w;
            }
        }
        __syncwarp();

        float logit = 0.f;
        #pragma unroll
        for (int j = 0; j < 8; ++j) logit += Pw[lane * 9 + j];

        float mx = logit;
        #pragma unroll
        for (int off = 16; off; off >>= 1)
            mx = fmaxf(mx, __shfl_xor_sync(FULL, mx, off));
        const float ex = __expf(logit - mx);
        float denom = ex;
        #pragma unroll
        for (int off = 16; off; off >>= 1)
            denom += __shfl_xor_sync(FULL, denom, off);
        const float prob = ex / denom;

        float o = 0.f;
        #pragma unroll 8
        for (int m = 0; m < N_MEM; ++m) {
            const int t_i = __shfl_sync(FULL, tidx, m);
            const float p = __shfl_sync(FULL, prob, m);
            o = fmaf(p, entity[t_i * DIM + lane], o);
        }

        const float tmp = item + o;
        float itn = 0.f;
        #pragma unroll
        for (int e = 0; e < DIM; ++e)
            itn = fmaf(__shfl_sync(FULL, tmp, e), g_Wt[e * DIM + lane], itn);

        if (!last) {
            g_item[b * DIM + lane] = itn;
            g_y[b * DIM + lane] = o;
            afrag_store(b, lane, itn);
        } else {
            const float y = g_y[b * DIM + lane] + o
                          + user_table[users[b] * DIM + lane];
            float s = itn * y;
            #pragma unroll
            for (int off = 16; off; off >>= 1)
                s += __shfl_xor_sync(FULL, s, off);
            if (lane == 0)
                out[b] = 1.f / (1.f + __expf(-s));
        }
        __syncwarp();
    }
}

// ---------------------------------------------------------------- kernel
__global__ void __launch_bounds__(256, 2) ripple_persistent(
    const int* __restrict__ items,
    const int* __restrict__ mem_h,
    const int* __restrict__ mem_r,
    const int* __restrict__ mem_t,
    const int* __restrict__ users,
    const float* __restrict__ entity,
    const float* __restrict__ relation,
    const float* __restrict__ user_table,
    const float* __restrict__ W,
    float* __restrict__ out)
{
    __shared__ __align__(16) char smem[8 * 16 * OSTR];   // 18 KB, phase-shared

    const int gtid = blockIdx.x * 256 + threadIdx.x;
    constexpr int T = NB * 256;   // 75776 threads

    // ---- phase 0: prep ----
    for (int i = gtid; i < BATCH * DIM; i += T) {
        const int b = i >> 5, e = i & 31;
        const float v = entity[items[b] * DIM + e];
        g_item[i] = v;
        afrag_store(b, e, v);
    }
    for (int i = gtid; i < (NCOL / 64) * 8 * 32 * 4; i += T) {
        const int nt = i >> 10, j = (i >> 7) & 7, l = (i >> 2) & 31, s = i & 3;
        const int n = nt * 64 + 8 * j + (l >> 2);
        const int r = n >> 5, e = n & 31;
        const int k0 = 2 * (l & 3) + 8 * s;
        const __nv_bfloat16 lo = __float2bfloat16(relation[r * 1024 + k0 * DIM + e]);
        const __nv_bfloat16 hi = __float2bfloat16(relation[r * 1024 + (k0 + 1) * DIM + e]);
        g_Bfrag[i] = ((unsigned)__bfloat16_as_ushort(hi) << 16) |
                     (unsigned)__bfloat16_as_ushort(lo);
    }
    if (gtid < DIM * DIM) {
        const int d = gtid >> 5, e = gtid & 31;
        g_Wt[e * DIM + d] = W[gtid];
    }

    grid_barrier();
    gemm_phase(smem);                                         // hop 0 GEMM
    grid_barrier();
    attn_phase(smem, mem_h, mem_r, mem_t, users, entity,
               user_table, out, 0, 0);                        // hop 0 attn
    grid_barrier();
    gemm_phase(smem);                                         // hop 1 GEMM
    grid_barrier();
    attn_phase(smem, mem_h, mem_r, mem_t, users, entity,
               user_table, out, 1, 1);                        // hop 1 attn + score
}

// ---------------------------------------------------------------- launch
extern "C" void kernel_launch(void* const* d_in, const int* in_sizes, int n_in,
                              void* d_out, int out_size) {
    const int*   items     = (const int*)d_in[0];
    const int*   mem_h     = (const int*)d_in[2];
    const int*   mem_r     = (const int*)d_in[3];
    const int*   mem_t     = (const int*)d_in[4];
    const int*   users     = (const int*)d_in[5];
    const float* entity    = (const float*)d_in[6];
    const float* relation  = (const float*)d_in[7];
    const float* user_tab  = (const float*)d_in[8];
    const float* W         = (const float*)d_in[9];
    float* out = (float*)d_out;

    ripple_persistent<<<NB, 256>>>(items, mem_h, mem_r, mem_t, users,
                                   entity, relation, user_tab, W, out);
}

// round 13
// speedup vs baseline: 1.3596x; 1.3596x over previous
#include <cuda_runtime.h>
#include <cuda_bf16.h>

#define FULL 0xFFFFFFFFu

constexpr int BATCH = 4096;
constexpr int DIM   = 32;
constexpr int N_MEM = 32;
constexpr int N_REL = 64;
constexpr int NCOL  = N_REL * DIM;   // 2048

// Static scratch (no runtime allocation allowed).
__device__ __nv_bfloat16  g_U[BATCH * NCOL];        // 16 MB bf16, LINEAR [b][n]
__device__ float          g_item[BATCH * DIM];
__device__ unsigned       g_Afrag[(BATCH / 16) * 2 * 32 * 4];   // A MMA frags
__device__ unsigned       g_Bfrag[(NCOL / 64) * 8 * 32 * 4];    // B MMA frags
__device__ float          g_Wt[DIM * DIM];
__device__ float          g_y[BATCH * DIM];

__device__ __forceinline__ float bf_lo(unsigned u) { return __uint_as_float(u << 16); }
__device__ __forceinline__ float bf_hi(unsigned u) { return __uint_as_float(u & 0xFFFF0000u); }

// Scatter one bf16 of the item vector into A-fragment layout.
__device__ __forceinline__ void afrag_store(int b, int e, float v) {
    const int mg = b >> 4, r = b & 15;
    const int h  = e >> 4, k = e & 15, kp = k >> 1;
    const int sel = ((r >> 3) & 1) + 2 * (kp >> 2);
    const int l   = (r & 7) * 4 + (kp & 3);
    const int idx = ((mg * 2 + h) * 32 + l) * 4 + sel;
    ((__nv_bfloat16*)g_Afrag)[idx * 2 + (k & 1)] = __float2bfloat16(v);
}

// ---------------------------------------------------------------- prep
__global__ void prep_kernel(const int* __restrict__ items,
                            const float* __restrict__ entity,
                            const float* __restrict__ relation,
                            const float* __restrict__ W) {
    const int i = blockIdx.x * blockDim.x + threadIdx.x;
    if (i < BATCH * DIM) {
        const int b = i >> 5, e = i & 31;
        const float v = entity[items[b] * DIM + e];
        g_item[i] = v;
        afrag_store(b, e, v);
    }
    if (i < (NCOL / 64) * 8 * 32 * 4) {
        const int nt = i >> 10, j = (i >> 7) & 7, l = (i >> 2) & 31, s = i & 3;
        const int n = nt * 64 + 8 * j + (l >> 2);
        const int r = n >> 5, e = n & 31;
        const int k0 = 2 * (l & 3) + 8 * s;
        const __nv_bfloat16 lo = __float2bfloat16(relation[r * 1024 + k0 * DIM + e]);
        const __nv_bfloat16 hi = __float2bfloat16(relation[r * 1024 + (k0 + 1) * DIM + e]);
        g_Bfrag[i] = ((unsigned)__bfloat16_as_ushort(hi) << 16) |
                     (unsigned)__bfloat16_as_ushort(lo);
    }
    if (i < DIM * DIM) {
        const int d = i >> 5, e = i & 31;
        g_Wt[e * DIM + d] = W[i];
    }
}

// ---------------------------------------------------------------- GEMM
__device__ __forceinline__ void mma16816(float c[4], const unsigned* a,
                                         unsigned b0, unsigned b1) {
    asm volatile(
        "mma.sync.aligned.m16n8k16.row.col.f32.bf16.bf16.f32 "
        "{%0,%1,%2,%3}, {%4,%5,%6,%7}, {%8,%9}, {%0,%1,%2,%3};\n"
        : "+f"(c[0]), "+f"(c[1]), "+f"(c[2]), "+f"(c[3])
        : "r"(a[0]), "r"(a[1]), "r"(a[2]), "r"(a[3]), "r"(b0), "r"(b1));
}

constexpr int OSTR = 144;   // bytes per sO row (128 payload + 16 pad)

// 256 blocks = exactly one wave. Block (mt, ng) computes n-tiles ng*4..ng*4+3
// of m-tile mt. A-frags loaded ONCE; B double-buffered at half-tile grain.
__global__ void __launch_bounds__(256, 3) gemm_kernel() {
    __shared__ __align__(16) char sO[8][16 * OSTR];   // per-warp slice, 18 KB

    const int lane = threadIdx.x & 31;
    const int warp = threadIdx.x >> 5;
    const int mt = blockIdx.x >> 3;
    const int ng = blockIdx.x & 7;
    const int mg = mt * 8 + warp;
    const int m0 = mt * 128;

    const uint4* __restrict__ Af = (const uint4*)g_Afrag;
    const uint4* __restrict__ Bf = (const uint4*)g_Bfrag;
    char* __restrict__ so = sO[warp];
    char* __restrict__ gU = (char*)g_U;

    const uint4 qa0 = Af[(mg * 2 + 0) * 32 + lane];   // k 0-15
    const uint4 qa1 = Af[(mg * 2 + 1) * 32 + lane];   // k 16-31

    // half-tile ht = 0..7: tile = ht>>1 (nt = ng*4+tile), j = (ht&1)*4 + jj
    uint4 buf[2][4];
    {
        const int nt = ng * 4;
        #pragma unroll
        for (int jj = 0; jj < 4; ++jj)
            buf[0][jj] = Bf[(nt * 8 + jj) * 32 + lane];
    }

    #pragma unroll
    for (int ht = 0; ht < 8; ++ht) {
        // prefetch next half-tile while computing this one
        if (ht < 7) {
            const int ntn = ng * 4 + ((ht + 1) >> 1);
            const int jb  = ((ht + 1) & 1) * 4;
            #pragma unroll
            for (int jj = 0; jj < 4; ++jj)
                buf[(ht + 1) & 1][jj] = Bf[(ntn * 8 + jb + jj) * 32 + lane];
        }

        const uint4* qb = buf[ht & 1];
        #pragma unroll
        for (int jj = 0; jj < 4; ++jj) {
            const int j = (ht & 1) * 4 + jj;
            float c[4] = {0.f, 0.f, 0.f, 0.f};
            mma16816(c, (const unsigned*)&qa0, qb[jj].x, qb[jj].y);
            mma16816(c, (const unsigned*)&qa1, qb[jj].z, qb[jj].w);
            const __nv_bfloat162 p01 = __float22bfloat162_rn(make_float2(c[0], c[1]));
            const __nv_bfloat162 p23 = __float22bfloat162_rn(make_float2(c[2], c[3]));
            const int row  = lane >> 2;
            const int colb = (8 * j + 2 * (lane & 3)) * 2;
            *(__nv_bfloat162*)(so + row * OSTR + colb)       = p01;
            *(__nv_bfloat162*)(so + (row + 8) * OSTR + colb) = p23;
        }

        if (ht & 1) {   // tile complete -> copy out 16x128B slice
            __syncwarp();
            const int n0 = (ng * 4 + (ht >> 1)) * 64;
            #pragma unroll
            for (int i = 0; i < 4; ++i) {
                const int idx = lane + 32 * i;
                const int row = idx >> 3, ch = idx & 7;
                const uint4 v = *(const uint4*)(so + row * OSTR + ch * 16);
                *(uint4*)(gU + ((size_t)(m0 + warp * 16 + row) * NCOL + n0) * 2
                          + ch * 16) = v;
            }
            __syncwarp();
        }
    }
}

// ---------------------------------------------------------------- attention
// 2 batch elements per warp (ILP-2), 8 warps per block -> 16 b per block.
constexpr int AW = 8;

__global__ void __launch_bounds__(256, 3) attn_kernel(
    const int* __restrict__ mem_h,
    const int* __restrict__ mem_r,
    const int* __restrict__ mem_t,
    const int* __restrict__ users,
    const float* __restrict__ entity,
    const float* __restrict__ user_table,
    float* __restrict__ out,
    int hop, int last)
{
    __shared__ float P[AW][2][N_MEM * 9];

    const int lane = threadIdx.x & 31;
    const int warp = threadIdx.x >> 5;
    const int b0 = (blockIdx.x * AW + warp) * 2;
    const int b1 = b0 + 1;
    float* __restrict__ P0 = P[warp][0];
    float* __restrict__ P1 = P[warp][1];

    const int base0 = hop * BATCH * N_MEM + b0 * N_MEM;
    const int base1 = base0 + N_MEM;
    const int hidx0 = mem_h[base0 + lane], hidx1 = mem_h[base1 + lane];
    const int ridx0 = mem_r[base0 + lane], ridx1 = mem_r[base1 + lane];
    const int tidx0 = mem_t[base0 + lane], tidx1 = mem_t[base1 + lane];

    const float item0 = g_item[b0 * DIM + lane];
    const float item1 = g_item[b1 * DIM + lane];

    // ---- partial dots: 4 sub-stages x (2 memories per b), 8 loads in flight ----
    const int mq = lane >> 3;
    const int c  = lane & 7;
    const __nv_bfloat16* __restrict__ U0 = g_U + (size_t)b0 * NCOL;
    const __nv_bfloat16* __restrict__ U1 = g_U + (size_t)b1 * NCOL;

    #pragma unroll
    for (int ss = 0; ss < 4; ++ss) {
        uint2  uu0[2], uu1[2];
        float4 h40[2], h41[2];
        #pragma unroll
        for (int it = 0; it < 2; ++it) {
            const int m = ss * 8 + it * 4 + mq;
            const int r0 = __shfl_sync(FULL, ridx0, m);
            const int h0 = __shfl_sync(FULL, hidx0, m);
            const int r1 = __shfl_sync(FULL, ridx1, m);
            const int h1 = __shfl_sync(FULL, hidx1, m);
            uu0[it] = *(const uint2*)(U0 + r0 * DIM + 4 * c);
            h40[it] = *(const float4*)(entity + h0 * DIM + 4 * c);
            uu1[it] = *(const uint2*)(U1 + r1 * DIM + 4 * c);
            h41[it] = *(const float4*)(entity + h1 * DIM + 4 * c);
        }
        #pragma unroll
        for (int it = 0; it < 2; ++it) {
            const int m = ss * 8 + it * 4 + mq;
            P0[m * 9 + c] = bf_lo(uu0[it].x) * h40[it].x + bf_hi(uu0[it].x) * h40[it].y +
                            bf_lo(uu0[it].y) * h40[it].z + bf_hi(uu0[it].y) * h40[it].w;
            P1[m * 9 + c] = bf_lo(uu1[it].x) * h41[it].x + bf_hi(uu1[it].x) * h41[it].y +
                            bf_lo(uu1[it].y) * h41[it].z + bf_hi(uu1[it].y) * h41[it].w;
        }
    }
    __syncwarp();

    // ---- logits (lane m owns memory m), both b's interleaved ----
    float lg0 = 0.f, lg1 = 0.f;
    #pragma unroll
    for (int j = 0; j < 8; ++j) { lg0 += P0[lane * 9 + j]; lg1 += P1[lane * 9 + j]; }

    // ---- softmax, two independent shfl chains ----
    float mx0 = lg0, mx1 = lg1;
    #pragma unroll
    for (int off = 16; off; off >>= 1) {
        mx0 = fmaxf(mx0, __shfl_xor_sync(FULL, mx0, off));
        mx1 = fmaxf(mx1, __shfl_xor_sync(FULL, mx1, off));
    }
    const float ex0 = __expf(lg0 - mx0);
    const float ex1 = __expf(lg1 - mx1);
    float dn0 = ex0, dn1 = ex1;
    #pragma unroll
    for (int off = 16; off; off >>= 1) {
        dn0 += __shfl_xor_sync(FULL, dn0, off);
        dn1 += __shfl_xor_sync(FULL, dn1, off);
    }
    const float prob0 = ex0 / dn0;
    const float prob1 = ex1 / dn1;

    // ---- o gathers, two chains interleaved ----
    float o0 = 0.f, o1 = 0.f;
    #pragma unroll 8
    for (int m = 0; m < N_MEM; ++m) {
        const int t0 = __shfl_sync(FULL, tidx0, m);
        const int t1 = __shfl_sync(FULL, tidx1, m);
        const float p0 = __shfl_sync(FULL, prob0, m);
        const float p1 = __shfl_sync(FULL, prob1, m);
        o0 = fmaf(p0, entity[t0 * DIM + lane], o0);
        o1 = fmaf(p1, entity[t1 * DIM + lane], o1);
    }

    // ---- item' = (item + o) @ W^T (Wt load shared by both b's) ----
    const float tmp0 = item0 + o0, tmp1 = item1 + o1;
    float itn0 = 0.f, itn1 = 0.f;
    #pragma unroll
    for (int e = 0; e < DIM; ++e) {
        const float w = g_Wt[e * DIM + lane];
        itn0 = fmaf(__shfl_sync(FULL, tmp0, e), w, itn0);
        itn1 = fmaf(__shfl_sync(FULL, tmp1, e), w, itn1);
    }

    if (!last) {
        g_item[b0 * DIM + lane] = itn0;
        g_item[b1 * DIM + lane] = itn1;
        g_y[b0 * DIM + lane] = o0;
        g_y[b1 * DIM + lane] = o1;
        afrag_store(b0, lane, itn0);
        afrag_store(b1, lane, itn1);
    } else {
        const float y0 = g_y[b0 * DIM + lane] + o0 + user_table[users[b0] * DIM + lane];
        const float y1 = g_y[b1 * DIM + lane] + o1 + user_table[users[b1] * DIM + lane];
        float s0 = itn0 * y0, s1 = itn1 * y1;
        #pragma unroll
        for (int off = 16; off; off >>= 1) {
            s0 += __shfl_xor_sync(FULL, s0, off);
            s1 += __shfl_xor_sync(FULL, s1, off);
        }
        if (lane == 0) {
            out[b0] = 1.f / (1.f + __expf(-s0));
            out[b1] = 1.f / (1.f + __expf(-s1));
        }
    }
}

// ---------------------------------------------------------------- launch
extern "C" void kernel_launch(void* const* d_in, const int* in_sizes, int n_in,
                              void* d_out, int out_size) {
    const int*   items     = (const int*)d_in[0];
    const int*   mem_h     = (const int*)d_in[2];
    const int*   mem_r     = (const int*)d_in[3];
    const int*   mem_t     = (const int*)d_in[4];
    const int*   users     = (const int*)d_in[5];
    const float* entity    = (const float*)d_in[6];
    const float* relation  = (const float*)d_in[7];
    const float* user_tab  = (const float*)d_in[8];
    const float* W         = (const float*)d_in[9];
    float* out = (float*)d_out;

    prep_kernel<<<(BATCH * DIM + 255) / 256, 256>>>(items, entity, relation, W);

    gemm_kernel<<<256, 256>>>();
    attn_kernel<<<BATCH / (AW * 2), 256>>>(mem_h, mem_r, mem_t, users,
                                           entity, user_tab, out, 0, 0);
    gemm_kernel<<<256, 256>>>();
    attn_kernel<<<BATCH / (AW * 2), 256>>>(mem_h, mem_r, mem_t, users,
                                           entity, user_tab, out, 1, 1);
}